// round 3
// baseline (speedup 1.0000x reference)
#include <cuda_runtime.h>

// Spatial correlation sampler:
// out[b, di*9+dj, i, j] = (1/C) * sum_c x[b,c,i,j] * y[b,c,i+di-4, j+dj-4]  (y zero-padded)
// Shapes: x,y = [16, 256, 64, 64] fp32; out = [16, 81, 64, 64] fp32.

#define BB 16
#define CH 256
#define HH 64
#define WW 64
#define TH 8          // output rows per block
#define CC 8          // channels per smem tile
#define DI_CHUNK 3    // displacement-rows per pass (grid.y = 3)
#define YR (TH + 2)   // y tile rows needed for 3 consecutive di (10)
#define YW 72         // y tile width: 64 + 2*4 padding

__global__ __launch_bounds__(128, 2)
void corr_kernel(const float* __restrict__ x,
                 const float* __restrict__ y,
                 float* __restrict__ out)
{
    __shared__ float xs[CC][TH][WW];   // 8*8*64*4  = 16 KB
    __shared__ float ys[CC][YR][YW];   // 8*10*72*4 = 22.5 KB

    const int tid = threadIdx.x;       // 128 threads
    const int jg  = tid & 15;          // 16 col-groups
    const int ti  = tid >> 4;          // 8 rows
    const int j0  = jg * 4;            // 4 pixels per thread (PX=4)
    const int i0  = blockIdx.x * TH;   // i-tile (8 tiles)
    const int g   = blockIdx.y * DI_CHUNK; // di base (0,3,6)
    const int b   = blockIdx.z;        // batch slowest -> L2 locality across passes

    float acc[DI_CHUNK][9][4];
#pragma unroll
    for (int a = 0; a < DI_CHUNK; a++)
#pragma unroll
        for (int d = 0; d < 9; d++)
#pragma unroll
            for (int p = 0; p < 4; p++) acc[a][d][p] = 0.0f;

    const float* xb = x + (size_t)b * CH * HH * WW;
    const float* yb = y + (size_t)b * CH * HH * WW;

    for (int cc0 = 0; cc0 < CH; cc0 += CC) {
        // ---- load x tile: CC*TH*WW = 4096 floats = 1024 float4, 8 per thread
#pragma unroll
        for (int e = 0; e < (CC * TH * WW / 4) / 128; e++) {
            int f    = tid + e * 128;          // float4 index
            int c    = f >> 7;                 // / (TH*WW/4 = 128)
            int rem  = f & 127;
            int r    = rem >> 4;
            int col4 = rem & 15;
            float4 v = *(const float4*)&xb[(size_t)(cc0 + c) * HH * WW + (i0 + r) * WW + col4 * 4];
            *(float4*)&xs[c][r][col4 * 4] = v;
        }
        // ---- load y tile: CC*YR*18 float4 = 1440, with zero padding at edges
        for (int f = tid; f < CC * YR * 18; f += 128) {
            int c   = f / (YR * 18);
            int rem = f % (YR * 18);
            int r   = rem / 18;
            int q   = rem % 18;
            int gy  = i0 + g - 4 + r;
            float4 v = make_float4(0.f, 0.f, 0.f, 0.f);
            if (gy >= 0 && gy < HH && q > 0 && q < 17) {
                v = *(const float4*)&yb[(size_t)(cc0 + c) * HH * WW + gy * WW + (q * 4 - 4)];
            }
            *(float4*)&ys[c][r][q * 4] = v;
        }
        __syncthreads();

        // ---- compute: per channel, 10 LDS.128 feed 108 FMAs (FMA-bound)
#pragma unroll
        for (int c = 0; c < CC; c++) {
            float4 xv = *(const float4*)&xs[c][ti][j0];
#pragma unroll
            for (int a = 0; a < DI_CHUNK; a++) {
                float w[12];
#pragma unroll
                for (int q = 0; q < 3; q++) {
                    float4 t = *(const float4*)&ys[c][ti + a][j0 + q * 4];
                    w[q * 4 + 0] = t.x; w[q * 4 + 1] = t.y;
                    w[q * 4 + 2] = t.z; w[q * 4 + 3] = t.w;
                }
#pragma unroll
                for (int d = 0; d < 9; d++) {
                    acc[a][d][0] += xv.x * w[d + 0];
                    acc[a][d][1] += xv.y * w[d + 1];
                    acc[a][d][2] += xv.z * w[d + 2];
                    acc[a][d][3] += xv.w * w[d + 3];
                }
            }
        }
        __syncthreads();
    }

    // ---- epilogue: scale by 1/C, vectorized coalesced stores
    const float s = 1.0f / (float)CH;
#pragma unroll
    for (int a = 0; a < DI_CHUNK; a++) {
#pragma unroll
        for (int d = 0; d < 9; d++) {
            int dd = (g + a) * 9 + d;
            float4 v = make_float4(acc[a][d][0] * s, acc[a][d][1] * s,
                                   acc[a][d][2] * s, acc[a][d][3] * s);
            *(float4*)&out[(((size_t)b * 81 + dd) * HH + (i0 + ti)) * WW + j0] = v;
        }
    }
}

extern "C" void kernel_launch(void* const* d_in, const int* in_sizes, int n_in,
                              void* d_out, int out_size)
{
    const float* x = (const float*)d_in[0];
    const float* y = (const float*)d_in[1];
    float* out = (float*)d_out;

    dim3 grid(HH / TH, 9 / DI_CHUNK, BB);   // (8, 3, 16); x fastest => batch-local scheduling
    dim3 block(128);
    corr_kernel<<<grid, block>>>(x, y, out);
}

// round 6
// speedup vs baseline: 1.4901x; 1.4901x over previous
#include <cuda_runtime.h>
#include <cstdint>

// Spatial correlation sampler:
// out[b, di*9+dj, i, j] = (1/C) * sum_c x[b,c,i,j] * y[b,c,i+di-4, j+dj-4]  (zero-padded)
// x,y = [16, 256, 64, 64] fp32; out = [16, 81, 64, 64] fp32.

#define BB 16
#define CH 256
#define HH 64
#define WW 64
#define TH 8          // output rows per CTA
#define CC 4          // channels per smem stage
#define NS (CH / CC)  // 64 stages
#define DI_CHUNK 3    // di rows per CTA (grid.y = 3)
#define YR (TH + 2)   // 10 y rows per stage
#define YW 72         // 64 + 2*4 pad
#define XF4 (CC * TH * WW / 4)   // 512 float4 per x stage
#define YF4 (CC * YR * 18)       // 720 float4 per y stage

#define FMA2(acc, a, b) \
    asm("fma.rn.f32x2 %0, %1, %2, %0;" : "+l"(acc) : "l"(a), "l"(b))
#define PACK2(r, lo, hi) \
    asm("mov.b64 %0, {%1, %2};" : "=l"(r) : "r"(__float_as_uint(lo)), "r"(__float_as_uint(hi)))
#define UNPK2(lo, hi, r) \
    asm("mov.b64 {%0, %1}, %2;" : "=f"(lo), "=f"(hi) : "l"(r))

__device__ __forceinline__ void cpa16(uint32_t saddr, const void* gptr, int src_bytes) {
    asm volatile("cp.async.cg.shared.global [%0], [%1], 16, %2;\n"
                 :: "r"(saddr), "l"(gptr), "r"(src_bytes));
}
__device__ __forceinline__ void cpa_commit() {
    asm volatile("cp.async.commit_group;\n");
}

__global__ __launch_bounds__(128, 2)
void corr_kernel(const float* __restrict__ x,
                 const float* __restrict__ y,
                 float* __restrict__ out)
{
    __shared__ float xs[2][CC][TH][WW];   // 2 * 8 KB
    __shared__ float ys[2][CC][YR][YW];   // 2 * 11.25 KB  => 38.5 KB total

    const int tid = threadIdx.x;       // 128 threads
    const int jg  = tid & 15;
    const int ti  = tid >> 4;
    const int j0  = jg * 4;            // 4 pixels per thread
    const int i0  = blockIdx.x * TH;
    const int g   = blockIdx.y * DI_CHUNK;
    const int b   = blockIdx.z;        // batch slowest -> L2 locality across passes

    const float* xb = x + (size_t)b * CH * HH * WW;
    const float* yb = y + (size_t)b * CH * HH * WW;

    const uint32_t xs_s = (uint32_t)__cvta_generic_to_shared(&xs[0][0][0][0]);
    const uint32_t ys_s = (uint32_t)__cvta_generic_to_shared(&ys[0][0][0][0]);
    const uint32_t xs_sz = sizeof(float) * CC * TH * WW;   // per-buffer bytes
    const uint32_t ys_sz = sizeof(float) * CC * YR * YW;

    // f32x2 accumulators: acc2[a][d][pair]
    unsigned long long acc2[DI_CHUNK][9][2];
#pragma unroll
    for (int a = 0; a < DI_CHUNK; a++)
#pragma unroll
        for (int d = 0; d < 9; d++) {
            acc2[a][d][0] = 0ull; acc2[a][d][1] = 0ull;
        }

    // ---- async stage loader: gmem -> smem[sel] for channel block `st`
    auto issue_stage = [&](int st, int sel) {
        const int cc0 = st * CC;
        // x tile: 512 float4, 4 per thread
#pragma unroll
        for (int e = 0; e < XF4 / 128; e++) {
            int f    = tid + e * 128;
            int c    = f >> 7;            // / (TH*WW/4 = 128)
            int rem  = f & 127;
            int r    = rem >> 4;
            int col4 = rem & 15;
            const float* g4 = &xb[(size_t)(cc0 + c) * HH * WW + (i0 + r) * WW + col4 * 4];
            cpa16(xs_s + sel * xs_sz + (uint32_t)f * 16u, g4, 16);
        }
        // y tile: 720 float4 with zero-padded edges
#pragma unroll
        for (int e = 0; e < 6; e++) {
            int f = tid + e * 128;
            if (f < YF4) {
                int c   = f / (YR * 18);
                int rem = f % (YR * 18);
                int r   = rem / 18;
                int q   = rem % 18;
                int gy  = i0 + g - 4 + r;
                bool ok = (gy >= 0) && (gy < HH) && (q > 0) && (q < 17);
                int gyc = gy < 0 ? 0 : (gy > HH - 1 ? HH - 1 : gy);
                int gq  = ok ? (q * 4 - 4) : 0;
                const float* g4 = &yb[(size_t)(cc0 + c) * HH * WW + gyc * WW + gq];
                uint32_t saddr = ys_s + sel * ys_sz
                               + (uint32_t)(((c * YR + r) * YW) + q * 4) * 4u;
                cpa16(saddr, g4, ok ? 16 : 0);
            }
        }
        cpa_commit();
    };

    issue_stage(0, 0);

    for (int it = 0; it < NS; it++) {
        const int sel = it & 1;
        if (it + 1 < NS) {
            issue_stage(it + 1, sel ^ 1);
            asm volatile("cp.async.wait_group 1;\n");
        } else {
            asm volatile("cp.async.wait_group 0;\n");
        }
        __syncthreads();

        // ---- compute on buffer `sel`
#pragma unroll
        for (int c = 0; c < CC; c++) {
            float4 xv = *(const float4*)&xs[sel][c][ti][j0];
            unsigned long long xlo, xhi;
            PACK2(xlo, xv.x, xv.y);
            PACK2(xhi, xv.z, xv.w);
#pragma unroll
            for (int a = 0; a < DI_CHUNK; a++) {
                float4 t0 = *(const float4*)&ys[sel][c][ti + a][j0 + 0];
                float4 t1 = *(const float4*)&ys[sel][c][ti + a][j0 + 4];
                float4 t2 = *(const float4*)&ys[sel][c][ti + a][j0 + 8];
                float wv[12] = { t0.x, t0.y, t0.z, t0.w,
                                 t1.x, t1.y, t1.z, t1.w,
                                 t2.x, t2.y, t2.z, t2.w };
                unsigned long long wp[11];
#pragma unroll
                for (int k = 0; k < 11; k++) PACK2(wp[k], wv[k], wv[k + 1]);
#pragma unroll
                for (int d = 0; d < 9; d++) {
                    FMA2(acc2[a][d][0], xlo, wp[d]);
                    FMA2(acc2[a][d][1], xhi, wp[d + 2]);
                }
            }
        }
        __syncthreads();
    }

    // ---- epilogue: scale by 1/C, coalesced float4 stores
    const float s = 1.0f / (float)CH;
#pragma unroll
    for (int a = 0; a < DI_CHUNK; a++) {
#pragma unroll
        for (int d = 0; d < 9; d++) {
            int dd = (g + a) * 9 + d;
            float v0, v1, v2, v3;
            UNPK2(v0, v1, acc2[a][d][0]);
            UNPK2(v2, v3, acc2[a][d][1]);
            float4 v = make_float4(v0 * s, v1 * s, v2 * s, v3 * s);
            *(float4*)&out[(((size_t)b * 81 + dd) * HH + (i0 + ti)) * WW + j0] = v;
        }
    }
}

extern "C" void kernel_launch(void* const* d_in, const int* in_sizes, int n_in,
                              void* d_out, int out_size)
{
    const float* x = (const float*)d_in[0];
    const float* y = (const float*)d_in[1];
    float* out = (float*)d_out;

    dim3 grid(HH / TH, 9 / DI_CHUNK, BB);   // (8, 3, 16)
    dim3 block(128);
    corr_kernel<<<grid, block>>>(x, y, out);
}